// round 17
// baseline (speedup 1.0000x reference)
#include <cuda_runtime.h>
#include <cuda_fp16.h>
#include <cstdint>

#define BATCH 16
#define TSEQ  4096
#define DIM   256
#define CH    64
#define NC    (TSEQ/CH)          // 64 chunks

typedef unsigned int u32;
typedef unsigned short u16;

// ---------------- device scratch (allocation-free rule) ----------------
__device__ float g_E[BATCH * NC * DIM];             // chunk-final LOCAL h
__device__ int   g_epoch[BATCH * NC];               // per-CTA launch counter
__device__ int   g_readyB;                          // += 16 per launch
__device__ int   g_readyC;                          // += 16 per launch
__device__ int   g_done[BATCH * NC];                // per-chunk epoch counters
// B / C pre-converted fp16 in mma fragment layout: [ks16][nt2_16][lane32][slot4]
__device__ __align__(16) u32 g_Bf[32768];
__device__ __align__(16) u32 g_Cf[32768];

// ---------------- helpers ----------------
__device__ __forceinline__ u16 f16_rn(float x) {
    return __half_as_ushort(__float2half_rn(x));
}
__device__ __forceinline__ u32 pack2(u16 a, u16 b) {
    return (u32)a | ((u32)b << 16);
}
__device__ __forceinline__ void mma_f16(float* c, const u32* a, u32 b0, u32 b1) {
    asm("mma.sync.aligned.m16n8k16.row.col.f32.f16.f16.f32 "
        "{%0,%1,%2,%3}, {%4,%5,%6,%7}, {%8,%9}, {%0,%1,%2,%3};"
        : "+f"(c[0]), "+f"(c[1]), "+f"(c[2]), "+f"(c[3])
        : "r"(a[0]), "r"(a[1]), "r"(a[2]), "r"(a[3]), "r"(b0), "r"(b1));
}

// ---------------- smem (disjoint regions) ----------------
// scanb: 64 x 260 floats = 66560 B at offset 0 (also converter transpose buffer)
// F    : fp16 A-fragments, 4 slabs x 8KB = 32768 B at offset 66560
#define OFF_F    66560
#define SMEM_SZ  (OFF_F + 32768)      // 99328 B; 2 CTA/SM fits 228KB carveout

// A-frag staging (fp16 rn), slab stride 8KB (2048 u32)
__device__ __forceinline__ void stage_A(u32* F, int row, int cp, float x, float y)
{
    int slab = row >> 4, rin = row & 15;
    int ks = cp >> 3, cpin = cp & 7;
    int lane = (rin & 7) * 4 + (cpin & 3);
    int reg  = ((cpin >> 2) << 1) | (rin >> 3);
    F[slab * 2048 + ((ks * 32 + lane) << 2) + reg] = pack2(f16_rn(x), f16_rn(y));
}

// Mainloop: warp tile m32 x n64 (2 M-slabs), single pass, B fp16 via LDG.
__device__ __forceinline__ void gemm_main(const u32* __restrict__ gBf,
                                          const u32* F,
                                          float acc[2][8][4], int wr, int wc, int lane)
{
    const u32* a0p = F + (wr * 2 + 0) * 2048 + lane * 4;
    const u32* a1p = F + (wr * 2 + 1) * 2048 + lane * 4;
    const u32* b_p = gBf + (wc * 4) * 128 + lane * 4;
    #pragma unroll
    for (int ks = 0; ks < 16; ++ks) {
        uint4 AH0 = *(const uint4*)(a0p + ks * 128);
        uint4 AH1 = *(const uint4*)(a1p + ks * 128);
        u32 ah[2][4] = {{AH0.x, AH0.y, AH0.z, AH0.w}, {AH1.x, AH1.y, AH1.z, AH1.w}};
        const u32* bp = b_p + ks * 2048;
        #pragma unroll
        for (int jp = 0; jp < 2; ++jp) {
            uint4 B0 = *(const uint4*)(bp + (2 * jp) * 128);
            uint4 B1 = *(const uint4*)(bp + (2 * jp + 1) * 128);
            #pragma unroll
            for (int s = 0; s < 2; ++s) {
                mma_f16(acc[s][4 * jp + 0], ah[s], B0.x, B0.y);
                mma_f16(acc[s][4 * jp + 1], ah[s], B0.z, B0.w);
                mma_f16(acc[s][4 * jp + 2], ah[s], B1.x, B1.y);
                mma_f16(acc[s][4 * jp + 3], ah[s], B1.z, B1.w);
            }
        }
    }
}

// ---------------------------------------------------------------------------
// kF: single fused launch.
//   bids 0..31 first convert one B/C k-slab (coalesced smem transpose).
//   GEMM1 gates only on the 16 B converters; C gate hides behind carry wait.
//   Epoch counters: graph-replay-safe, no reset pass.
//   grid (b=16, c=64): bid = c*16 + b, dependencies have smaller bids.
// ---------------------------------------------------------------------------
__global__ __launch_bounds__(256, 2) void kF(
    const float* __restrict__ U, const float* __restrict__ A,
    const float* __restrict__ h0v, float* __restrict__ Y,
    const float* __restrict__ Bm, const float* __restrict__ Cm)
{
    extern __shared__ __align__(16) char smem[];
    float* scanb = (float*)smem;
    u32* F = (u32*)(smem + OFF_F);
    __shared__ int sL;

    const int tid = threadIdx.x, wid = tid >> 5, lane = tid & 31;
    const int wr = wid & 1, wc = wid >> 1;
    const int b = blockIdx.x, c = blockIdx.y;
    const int bid = c * BATCH + b;
    const int t0 = c * CH;

    if (tid == 0) sL = atomicAdd(&g_epoch[bid], 1) + 1;

    // ---- converter CTAs: one k-slab of B (bid<16) or C (16<=bid<32)
    if (bid < 32) {
        const float* src = (bid < 16) ? Bm : Cm;
        u32* dst         = (bid < 16) ? g_Bf : g_Cf;
        const int ks = bid & 15;
        u32* sT  = (u32*)smem;            // [256][9] u32 transpose buffer
        u16* sT16 = (u16*)sT;             // index = n*18 + kk
        const float4* s4 = (const float4*)(src + (size_t)ks * 16 * DIM);
        #pragma unroll
        for (int i = 0; i < 4; ++i) {
            int idx = tid + i * 256;      // 16 rows x 64 quads
            int kk = idx >> 6, q = idx & 63;
            float4 v = s4[idx];
            sT16[(4 * q + 0) * 18 + kk] = f16_rn(v.x);
            sT16[(4 * q + 1) * 18 + kk] = f16_rn(v.y);
            sT16[(4 * q + 2) * 18 + kk] = f16_rn(v.z);
            sT16[(4 * q + 3) * 18 + kk] = f16_rn(v.w);
        }
        __syncthreads();
        #pragma unroll
        for (int i = 0; i < 8; ++i) {
            int fi = tid + i * 256;
            int slot  = fi & 3;
            int lane2 = (fi >> 2) & 31;
            int nt2   = (fi >> 7) & 15;
            int ntlow = slot >> 1, breg = slot & 1;
            int n  = (nt2 * 2 + ntlow) * 8 + (lane2 >> 2);
            int kp = (lane2 & 3) + breg * 4;       // k-pair index 0..7
            dst[ks * 2048 + fi] = sT[n * 9 + kp];
        }
        __syncthreads();
        if (tid == 0) {
            __threadfence();
            atomicAdd((bid < 16) ? &g_readyB : &g_readyC, 1);
        }
        __syncthreads();                 // transpose buffer dead after this
    }

    // ---- stage U tile as fp16 A-fragments
    {
        const float* ub = U + ((size_t)b * TSEQ + t0) * DIM;
        #pragma unroll
        for (int it = 0; it < 32; ++it) {
            int idx = tid + it * 256;          // 8192 = 64 rows x 128 colpairs
            int row = idx >> 7, cp = idx & 127;
            float2 v = *(const float2*)(ub + (size_t)row * DIM + cp * 2);
            stage_A(F, row, cp, v.x, v.y);
        }
    }
    __syncthreads();
    const int L = sL;

    // ---- wait for the 16 B converters of this launch
    if (tid == 0) {
        while (atomicAdd(&g_readyB, 0) < 16 * L) __nanosleep(32);
        __threadfence();
    }
    __syncthreads();

    float acc[2][8][4];
    #pragma unroll
    for (int s = 0; s < 2; ++s)
        #pragma unroll
        for (int i = 0; i < 8; ++i) {
            acc[s][i][0]=0.f; acc[s][i][1]=0.f; acc[s][i][2]=0.f; acc[s][i][3]=0.f;
        }
    gemm_main(g_Bf, F, acc, wr, wc, lane);

    // acc -> scanb (state-major for the scan), float2 stores
    #pragma unroll
    for (int s = 0; s < 2; ++s) {
        int r0 = (wr * 2 + s) * 16 + (lane >> 2);
        #pragma unroll
        for (int a = 0; a < 8; ++a) {
            int col = wc * 64 + (a >> 1) * 16 + (a & 1) * 8 + (lane & 3) * 2;
            *(float2*)(scanb + r0 * 260 + col) =
                make_float2(acc[s][a][0], acc[s][a][1]);
            *(float2*)(scanb + (r0 + 8) * 260 + col) =
                make_float2(acc[s][a][2], acc[s][a][3]);
        }
    }
    __syncthreads();

    // ---- pass 1: local E only (software-pipelined: load 8 ahead)
    const float a = A[tid];
    {
        float h = 0.f;
        float buf[8], nxt[8];
        #pragma unroll
        for (int i = 0; i < 8; ++i) buf[i] = scanb[i * 260 + tid];
        #pragma unroll
        for (int g = 0; g < 8; ++g) {
            if (g < 7) {
                #pragma unroll
                for (int i = 0; i < 8; ++i)
                    nxt[i] = scanb[((g + 1) * 8 + i) * 260 + tid];
            }
            #pragma unroll
            for (int i = 0; i < 8; ++i) h = fmaf(h, a, buf[i]);
            #pragma unroll
            for (int i = 0; i < 8; ++i) buf[i] = nxt[i];
        }
        g_E[((size_t)b * NC + c) * DIM + tid] = h;
    }
    __syncthreads();
    if (tid == 0) {
        __threadfence();
        atomicAdd(&g_done[b * NC + c], 1);
    }

    // ---- wait for all earlier chunks of this batch (parallel polls)
    if (tid < c) {
        while (atomicAdd(&g_done[b * NC + tid], 0) < L) __nanosleep(32);
    }
    // ---- and for the 16 C converters (hidden behind the chunk wait)
    if (tid == 255) {
        while (atomicAdd(&g_readyC, 0) < 16 * L) __nanosleep(32);
        __threadfence();
    }
    __syncthreads();

    // ---- carry: scan of earlier chunks' E, batched loads (MLP=4)
    float carry = h0v[tid];
    {
        float p = a;
        #pragma unroll
        for (int i = 0; i < 6; ++i) p = p * p;          // a^64
        const float* Eb = g_E + (size_t)b * NC * DIM + tid;
        int j = 0;
        for (; j + 4 <= c; j += 4) {
            float e0 = Eb[(size_t)(j + 0) * DIM];
            float e1 = Eb[(size_t)(j + 1) * DIM];
            float e2 = Eb[(size_t)(j + 2) * DIM];
            float e3 = Eb[(size_t)(j + 3) * DIM];
            carry = fmaf(p, carry, e0);
            carry = fmaf(p, carry, e1);
            carry = fmaf(p, carry, e2);
            carry = fmaf(p, carry, e3);
        }
        for (; j < c; ++j)
            carry = fmaf(p, carry, Eb[(size_t)j * DIM]);
    }

    // ---- pass 2: exact scan seeded with carry; frag writes via lane-pair shfl
    {
        const int cp = tid >> 1;
        const int ks = cp >> 3, cpin = cp & 7;
        const int lbase = (cpin & 3);
        const int rsel  = ((cpin >> 2) << 1);
        float h = carry;
        float buf[8], nxt[8];
        #pragma unroll
        for (int i = 0; i < 8; ++i) buf[i] = scanb[i * 260 + tid];
        #pragma unroll
        for (int g = 0; g < 8; ++g) {
            if (g < 7) {
                #pragma unroll
                for (int i = 0; i < 8; ++i)
                    nxt[i] = scanb[((g + 1) * 8 + i) * 260 + tid];
            }
            #pragma unroll
            for (int i = 0; i < 8; ++i) {
                int t = g * 8 + i;
                h = fmaf(h, a, buf[i]);
                u32 mine = f16_rn(h);
                u32 part = __shfl_xor_sync(0xffffffffu, mine, 1);
                if (!(tid & 1)) {
                    int slab = t >> 4, rin = t & 15;
                    int lane2 = (rin & 7) * 4 + lbase;
                    int reg   = rsel | (rin >> 3);
                    F[slab * 2048 + ((ks * 32 + lane2) << 2) + reg] =
                        pack2((u16)mine, (u16)part);
                }
            }
            #pragma unroll
            for (int i = 0; i < 8; ++i) buf[i] = nxt[i];
        }
    }
    __syncthreads();

    // ---- GEMM with C
    #pragma unroll
    for (int s = 0; s < 2; ++s)
        #pragma unroll
        for (int i = 0; i < 8; ++i) {
            acc[s][i][0]=0.f; acc[s][i][1]=0.f; acc[s][i][2]=0.f; acc[s][i][3]=0.f;
        }
    gemm_main(g_Cf, F, acc, wr, wc, lane);

    // ---- epilogue: store acc directly to Y (float2, full-sector STG)
    {
        float* yb = Y + ((size_t)b * TSEQ + t0) * DIM;
        #pragma unroll
        for (int s = 0; s < 2; ++s) {
            int r0 = (wr * 2 + s) * 16 + (lane >> 2);
            #pragma unroll
            for (int aa = 0; aa < 8; ++aa) {
                int col = wc * 64 + (aa >> 1) * 16 + (aa & 1) * 8 + (lane & 3) * 2;
                *(float2*)(yb + (size_t)r0 * DIM + col) =
                    make_float2(acc[s][aa][0], acc[s][aa][1]);
                *(float2*)(yb + (size_t)(r0 + 8) * DIM + col) =
                    make_float2(acc[s][aa][2], acc[s][aa][3]);
            }
        }
    }
}

// ---------------------------------------------------------------------------

extern "C" void kernel_launch(void* const* d_in, const int* in_sizes, int n_in,
                              void* d_out, int out_size)
{
    const float* U  = (const float*)d_in[0];
    const float* A  = (const float*)d_in[1];
    const float* Bm = (const float*)d_in[2];
    const float* Cm = (const float*)d_in[3];
    const float* h0 = (const float*)d_in[4];
    float* Y = (float*)d_out;
    (void)in_sizes; (void)n_in; (void)out_size;

    cudaFuncSetAttribute(kF, cudaFuncAttributeMaxDynamicSharedMemorySize, SMEM_SZ);

    kF<<<dim3(BATCH, NC), 256, SMEM_SZ>>>(U, A, h0, Y, Bm, Cm);
}